// round 2
// baseline (speedup 1.0000x reference)
#include <cuda_runtime.h>
#include <cstdint>
#include <cstddef>

// Problem constants
#define B_    256
#define S_    512
#define EMB_  256
#define KER_  5
#define NF_   256
#define HID_  128
#define T_    508            // S - KER + 1
#define M_    (T_ * B_)      // 130048 rows (r = t*B + b)
#define KCONV (KER_ * EMB_)  // 1280
#define GATES 512            // 4*HID

// Scratch (static __device__ arrays: allocation-free per harness rules)
__device__ float g_E [(size_t)B_ * S_ * EMB_];   // embedded text [b][s][e]
__device__ float g_F [(size_t)M_ * NF_];         // conv+relu    [r][nf]
__device__ float g_Xg[(size_t)M_ * GATES];       // x-gates+bias [r][4H]
__device__ float g_h [2][B_ * HID_];             // double-buffered hidden
__device__ float g_c [B_ * HID_];                // cell state

// ---------------------------------------------------------------------------
// K0: embedding gather. E[b][s][:] = emb[text[b][s]][:]
// ---------------------------------------------------------------------------
__global__ void gather_kernel(const int* __restrict__ text,
                              const float* __restrict__ emb) {
  int idx = blockIdx.x * blockDim.x + threadIdx.x;   // over B*S*64 float4
  int row = idx >> 6;
  int c4  = idx & 63;
  int tok = text[row];
  ((float4*)g_E)[(size_t)row * 64 + c4] =
      ((const float4*)emb)[(size_t)tok * 64 + c4];
}

// ---------------------------------------------------------------------------
// K1/K2: tiled SIMT SGEMM, BM=BN=128, BK=16, 256 threads, 8x8 per thread.
//   IS_CONV: A row r -> &g_E[((r&255)*S + (r>>8)) * EMB], contiguous 1280
//            (overlapping conv windows ARE contiguous rows of E)
//            epilogue: relu(acc + conv_b[n]) -> g_F
//   else   : A row r -> &g_F[r*256], epilogue: acc + b_ih[n] + b_hh[n] -> g_Xg
//   Weights W are [N][K] row-major (matches conv_w and w_ih memory layout).
// ---------------------------------------------------------------------------
template<bool IS_CONV>
__global__ void __launch_bounds__(256)
sgemm_kernel(const float* __restrict__ W,
             const float* __restrict__ bias0,
             const float* __restrict__ bias1,
             int Kdim, int Ndim) {
  __shared__ float As[16][128];
  __shared__ float Bs[16][128];

  const int tid  = threadIdx.x;
  const int row0 = blockIdx.y * 128;
  const int col0 = blockIdx.x * 128;
  const int tr   = (tid >> 4) << 3;   // 0..120
  const int tc   = (tid & 15) << 3;   // 0..120

  float acc[8][8];
#pragma unroll
  for (int i = 0; i < 8; i++)
#pragma unroll
    for (int j = 0; j < 8; j++) acc[i][j] = 0.f;

  const float* Abase = IS_CONV ? g_E : g_F;
  const int kq = (tid & 3) * 4;       // k sub-offset this thread loads

  size_t aoff[2];
#pragma unroll
  for (int i = 0; i < 2; i++) {
    int m = (tid >> 2) + i * 64;
    int r = row0 + m;
    if (IS_CONV) {
      int b = r & 255, t = r >> 8;
      aoff[i] = ((size_t)b * S_ + t) * EMB_;
    } else {
      aoff[i] = (size_t)r * Kdim;
    }
  }

  for (int k0 = 0; k0 < Kdim; k0 += 16) {
#pragma unroll
    for (int i = 0; i < 2; i++) {
      int m = (tid >> 2) + i * 64;
      float4 va = *(const float4*)(Abase + aoff[i] + k0 + kq);
      As[kq + 0][m] = va.x; As[kq + 1][m] = va.y;
      As[kq + 2][m] = va.z; As[kq + 3][m] = va.w;
      float4 vb = *(const float4*)(W + (size_t)(col0 + m) * Kdim + k0 + kq);
      Bs[kq + 0][m] = vb.x; Bs[kq + 1][m] = vb.y;
      Bs[kq + 2][m] = vb.z; Bs[kq + 3][m] = vb.w;
    }
    __syncthreads();
#pragma unroll
    for (int kk = 0; kk < 16; kk++) {
      float a[8], b[8];
      *(float4*)&a[0] = *(const float4*)&As[kk][tr];
      *(float4*)&a[4] = *(const float4*)&As[kk][tr + 4];
      *(float4*)&b[0] = *(const float4*)&Bs[kk][tc];
      *(float4*)&b[4] = *(const float4*)&Bs[kk][tc + 4];
#pragma unroll
      for (int i = 0; i < 8; i++)
#pragma unroll
        for (int j = 0; j < 8; j++) acc[i][j] += a[i] * b[j];
    }
    __syncthreads();
  }

  float* C = IS_CONV ? g_F : g_Xg;
#pragma unroll
  for (int i = 0; i < 8; i++) {
    size_t crow = (size_t)(row0 + tr + i) * Ndim;
#pragma unroll
    for (int j = 0; j < 8; j++) {
      int n = col0 + tc + j;
      float v = acc[i][j] + bias0[n];
      if (IS_CONV) v = fmaxf(v, 0.f);
      else         v += bias1[n];
      C[crow + n] = v;
    }
  }
}

// ---------------------------------------------------------------------------
// K3: one LSTM step. Grid (8,8): CTA = 32 batch x 16 hidden (x 4 gates).
// h double-buffered across launches (no intra-launch races); c owned
// exclusively per (b,j) by one thread. W_hh tile staged in smem, layout
// [g][jj][132] (pad 132 => bank stride 4, conflict-free float4 loads).
// ---------------------------------------------------------------------------
#define STEP_SMEM ((32 * 128 + 4 * 16 * 132) * 4)   // 50176 B (dynamic)

__global__ void __launch_bounds__(256)
lstm_step_kernel(int t, const float* __restrict__ w_hh) {
  extern __shared__ float sm[];
  float* hs = sm;               // [32][128]
  float* Ws = sm + 32 * 128;    // [4][16][132]

  const float* h_in  = g_h[t & 1];
  float*       h_out = g_h[(t & 1) ^ 1];
  const int bi = blockIdx.x;    // batch tile (32 rows)
  const int hj = blockIdx.y;    // hidden tile (16 units)
  const int tid = threadIdx.x;

  {
    const float4* src = (const float4*)(h_in + bi * 32 * HID_);
    float4* dst = (float4*)hs;
    for (int i = tid; i < 1024; i += 256) dst[i] = src[i];
  }
  for (int i = tid; i < 2048; i += 256) {          // 8192 floats as float4
    int rowi = i >> 5, k4 = i & 31;
    int g = rowi >> 4, jj = rowi & 15;
    float4 v = ((const float4*)w_hh)[(size_t)(g * 128 + hj * 16 + jj) * 32 + k4];
    *(float4*)&Ws[(size_t)(g * 16 + jj) * 132 + k4 * 4] = v;
  }
  __syncthreads();

  const int jj = tid & 15;      // hidden within tile
  const int bp = tid >> 4;      // 0..15 -> batch pair
  const float* h0p = hs + (2 * bp) * 128;
  const float* h1p = h0p + 128;

  float acc[2][4];
#pragma unroll
  for (int i = 0; i < 2; i++)
#pragma unroll
    for (int g = 0; g < 4; g++) acc[i][g] = 0.f;

#pragma unroll 8
  for (int k = 0; k < 128; k += 4) {
    float4 h0 = *(const float4*)(h0p + k);
    float4 h1 = *(const float4*)(h1p + k);
#pragma unroll
    for (int g = 0; g < 4; g++) {
      float4 w = *(const float4*)&Ws[(size_t)(g * 16 + jj) * 132 + k];
      acc[0][g] += h0.x * w.x + h0.y * w.y + h0.z * w.z + h0.w * w.w;
      acc[1][g] += h1.x * w.x + h1.y * w.y + h1.z * w.z + h1.w * w.w;
    }
  }

  const int j = hj * 16 + jj;
#pragma unroll
  for (int i = 0; i < 2; i++) {
    int b = bi * 32 + 2 * bp + i;
    const float* xg = g_Xg + ((size_t)t * B_ + b) * GATES;
    float xi = acc[i][0] + xg[          j];
    float xf = acc[i][1] + xg[HID_    + j];
    float xc = acc[i][2] + xg[2*HID_  + j];
    float xo = acc[i][3] + xg[3*HID_  + j];
    float ig = 1.f / (1.f + __expf(-xi));
    float fg = 1.f / (1.f + __expf(-xf));
    float gg = tanhf(xc);
    float og = 1.f / (1.f + __expf(-xo));
    int ci = b * HID_ + j;
    float c = fg * g_c[ci] + ig * gg;
    g_c[ci] = c;
    h_out[ci] = og * tanhf(c);
  }
}

// ---------------------------------------------------------------------------
__global__ void init_kernel(const float* __restrict__ h0) {
  int i = blockIdx.x * blockDim.x + threadIdx.x;   // 32768 threads
  g_h[0][i] = h0[i];
  g_c[i] = 0.f;
}

__global__ void final_kernel(float* __restrict__ out) {
  int i = blockIdx.x * blockDim.x + threadIdx.x;
  out[i] = g_h[0][i];   // after 508 (even) steps, latest h is in buffer 0
}

// ---------------------------------------------------------------------------
extern "C" void kernel_launch(void* const* d_in, const int* in_sizes, int n_in,
                              void* d_out, int out_size) {
  const int*   text   = (const int*)  d_in[0];
  const float* h0     = (const float*)d_in[1];
  const float* emb    = (const float*)d_in[2];
  const float* conv_w = (const float*)d_in[3];
  const float* conv_b = (const float*)d_in[4];
  const float* w_ih   = (const float*)d_in[5];
  const float* w_hh   = (const float*)d_in[6];
  const float* b_ih   = (const float*)d_in[7];
  const float* b_hh   = (const float*)d_in[8];

  // 50KB dynamic smem for the step kernel (idempotent; also set on the
  // uncaptured correctness call, so it's in effect before capture).
  cudaFuncSetAttribute(lstm_step_kernel,
                       cudaFuncAttributeMaxDynamicSharedMemorySize, STEP_SMEM);

  // K0: gather embeddings
  gather_kernel<<<(B_ * S_ * 64) / 256, 256>>>(text, emb);

  // K1: conv as GEMM [130048 x 1280] x [1280 x 256] + bias + relu
  sgemm_kernel<true ><<<dim3(NF_   / 128, M_ / 128), 256>>>(
      conv_w, conv_b, nullptr, KCONV, NF_);

  // K2: x-gates GEMM [130048 x 256] x [256 x 512] + b_ih + b_hh
  sgemm_kernel<false><<<dim3(GATES / 128, M_ / 128), 256>>>(
      w_ih, b_ih, b_hh, NF_, GATES);

  // K3: recurrence, 508 sequential in-graph launches, h double-buffered
  init_kernel<<<128, 256>>>(h0);
  for (int t = 0; t < T_; t++)
    lstm_step_kernel<<<dim3(8, 8), 256, STEP_SMEM>>>(t, w_hh);

  final_kernel<<<128, 256>>>((float*)d_out);
}

// round 3
// speedup vs baseline: 1.4835x; 1.4835x over previous
#include <cuda_runtime.h>
#include <cstdint>
#include <cstddef>

// Problem constants
#define B_    256
#define S_    512
#define EMB_  256
#define KER_  5
#define NF_   256
#define HID_  128
#define T_    508            // S - KER + 1
#define M_    (T_ * B_)      // 130048 rows (r = t*B + b)
#define KCONV (KER_ * EMB_)  // 1280
#define GATES 512            // 4*HID
#define NCTA  128            // persistent recurrence grid

// Scratch (static __device__ arrays: allocation-free per harness rules)
__device__ float g_E [(size_t)B_ * S_ * EMB_];   // embedded text [b][s][e]
__device__ float g_F [(size_t)M_ * NF_];         // conv+relu    [r][nf]
__device__ float g_Xg[(size_t)M_ * GATES];       // x-gates+bias [r][4H]
__device__ float g_h [2][B_ * HID_];             // ping-pong hidden state
__device__ unsigned g_arrive;                    // grid-barrier arrival count
__device__ volatile unsigned g_release;          // grid-barrier release flag

// ---------------------------------------------------------------------------
// K0: embedding gather. E[b][s][:] = emb[text[b][s]][:]
// ---------------------------------------------------------------------------
__global__ void gather_kernel(const int* __restrict__ text,
                              const float* __restrict__ emb) {
  int idx = blockIdx.x * blockDim.x + threadIdx.x;   // over B*S*64 float4
  int row = idx >> 6;
  int c4  = idx & 63;
  int tok = text[row];
  ((float4*)g_E)[(size_t)row * 64 + c4] =
      ((const float4*)emb)[(size_t)tok * 64 + c4];
}

// ---------------------------------------------------------------------------
// K1/K2: tiled SGEMM, BM=BN=128, BK=16, 256 threads, 8x8/thread,
// DOUBLE-BUFFERED smem (one __syncthreads per k-tile), 2 CTAs/SM.
//   IS_CONV: A row r -> &g_E[((r&255)*S + (r>>8)) * EMB]  (windows contiguous)
//            epilogue: relu(acc + conv_b[n]) -> g_F
//   else   : A row r -> &g_F[r*256], epilogue: acc + b_ih + b_hh -> g_Xg
//   W is [N][K] row-major.
// ---------------------------------------------------------------------------
template<bool IS_CONV>
__global__ void __launch_bounds__(256, 2)
sgemm_kernel(const float* __restrict__ W,
             const float* __restrict__ bias0,
             const float* __restrict__ bias1,
             int Kdim, int Ndim) {
  __shared__ float As[2][16][128];
  __shared__ float Bs[2][16][128];

  const int tid  = threadIdx.x;
  const int row0 = blockIdx.y * 128;
  const int col0 = blockIdx.x * 128;
  const int tr   = (tid >> 4) << 3;   // 0..120
  const int tc   = (tid & 15) << 3;   // 0..120
  const int ms   = tid >> 2;          // staged row 0..63 (+64)
  const int kq   = (tid & 3) * 4;     // staged k sub-offset

  float acc[8][8];
#pragma unroll
  for (int i = 0; i < 8; i++)
#pragma unroll
    for (int j = 0; j < 8; j++) acc[i][j] = 0.f;

  const float* Abase = IS_CONV ? g_E : g_F;

  size_t aoff[2], boff[2];
#pragma unroll
  for (int i = 0; i < 2; i++) {
    int m = ms + i * 64;
    int r = row0 + m;
    if (IS_CONV) {
      int b = r & 255, t = r >> 8;
      aoff[i] = ((size_t)b * S_ + t) * EMB_;
    } else {
      aoff[i] = (size_t)r * Kdim;
    }
    boff[i] = (size_t)(col0 + m) * Kdim;
  }

  const int KT = Kdim >> 4;

  // prologue: tile 0 -> smem[0]
  {
    float4 pa[2], pb[2];
#pragma unroll
    for (int i = 0; i < 2; i++) {
      pa[i] = *(const float4*)(Abase + aoff[i] + kq);
      pb[i] = *(const float4*)(W + boff[i] + kq);
    }
#pragma unroll
    for (int i = 0; i < 2; i++) {
      int m = ms + i * 64;
      As[0][kq + 0][m] = pa[i].x; As[0][kq + 1][m] = pa[i].y;
      As[0][kq + 2][m] = pa[i].z; As[0][kq + 3][m] = pa[i].w;
      Bs[0][kq + 0][m] = pb[i].x; Bs[0][kq + 1][m] = pb[i].y;
      Bs[0][kq + 2][m] = pb[i].z; Bs[0][kq + 3][m] = pb[i].w;
    }
  }
  __syncthreads();

  for (int kt = 0; kt < KT; kt++) {
    const int cur = kt & 1;
    float4 pa[2], pb[2];
    const bool pf = (kt + 1 < KT);
    if (pf) {
      int k0 = (kt + 1) << 4;
#pragma unroll
      for (int i = 0; i < 2; i++) {
        pa[i] = *(const float4*)(Abase + aoff[i] + k0 + kq);
        pb[i] = *(const float4*)(W + boff[i] + k0 + kq);
      }
    }
#pragma unroll
    for (int kk = 0; kk < 16; kk++) {
      float a[8], b[8];
      *(float4*)&a[0] = *(const float4*)&As[cur][kk][tr];
      *(float4*)&a[4] = *(const float4*)&As[cur][kk][tr + 4];
      *(float4*)&b[0] = *(const float4*)&Bs[cur][kk][tc];
      *(float4*)&b[4] = *(const float4*)&Bs[cur][kk][tc + 4];
#pragma unroll
      for (int i = 0; i < 8; i++)
#pragma unroll
        for (int j = 0; j < 8; j++) acc[i][j] += a[i] * b[j];
    }
    if (pf) {
      const int nxt = cur ^ 1;
#pragma unroll
      for (int i = 0; i < 2; i++) {
        int m = ms + i * 64;
        As[nxt][kq + 0][m] = pa[i].x; As[nxt][kq + 1][m] = pa[i].y;
        As[nxt][kq + 2][m] = pa[i].z; As[nxt][kq + 3][m] = pa[i].w;
        Bs[nxt][kq + 0][m] = pb[i].x; Bs[nxt][kq + 1][m] = pb[i].y;
        Bs[nxt][kq + 2][m] = pb[i].z; Bs[nxt][kq + 3][m] = pb[i].w;
      }
    }
    __syncthreads();
  }

  float* C = IS_CONV ? g_F : g_Xg;
#pragma unroll
  for (int i = 0; i < 8; i++) {
    size_t crow = (size_t)(row0 + tr + i) * Ndim;
#pragma unroll
    for (int j = 0; j < 8; j++) {
      int n = col0 + tc + j;
      float v = acc[i][j] + bias0[n];
      if (IS_CONV) v = fmaxf(v, 0.f);
      else         v += bias1[n];
      C[crow + n] = v;
    }
  }
}

// ---------------------------------------------------------------------------
// K3: persistent LSTM recurrence. 128 CTAs x 128 threads, all co-resident
// (grid < #SMs) -> manual grid barrier is safe. CTA = 32 batch x 8 hidden.
// W_hh tile resident in smem for all 508 steps; c resident in REGISTERS;
// h ping-pongs through L2 (__ldcg reads avoid stale L1). Padded smem rows
// (stride 132) => all LDS.128 conflict-free. Final h written straight to out.
// ---------------------------------------------------------------------------
__global__ void __launch_bounds__(128)
lstm_persist_kernel(const float* __restrict__ w_hh,
                    float* __restrict__ out) {
  __shared__ float hs[32 * 132];     // h tile [b][k], padded
  __shared__ float Ws[32 * 132];     // W tile [g*8+jl][k], padded

  const int tid = threadIdx.x;
  const int bi  = blockIdx.x & 7;    // batch tile (32 rows)
  const int jt  = blockIdx.x >> 3;   // hidden tile (8 units)

  // Load W_hh tile once (4 gates x 8 j x 128 k = 1024 float4)
  for (int i = tid; i < 1024; i += 128) {
    int rowi = i >> 5, k4 = i & 31;              // rowi = g*8 + jl
    int g = rowi >> 3, jl = rowi & 7;
    float4 v = ((const float4*)w_hh)[(size_t)(g * 128 + jt * 8 + jl) * 32 + k4];
    *(float4*)&Ws[rowi * 132 + k4 * 4] = v;
  }

  const int jl = tid & 7;            // hidden within tile
  const int bp = tid >> 3;           // 0..15 -> batch pair
  const int jg = jt * 8 + jl;        // global hidden index
  const int b0 = bi * 32 + 2 * bp;   // global batch (first of pair)

  float c0 = 0.f, c1 = 0.f;          // cell state lives in registers

  for (int t = 0; t < T_; t++) {
    // stage h_in tile (L2-coherent reads)
    const float4* src = (const float4*)(g_h[t & 1] + bi * 32 * HID_);
    for (int i = tid; i < 1024; i += 128) {
      float4 v = __ldcg(src + i);
      int b = i >> 5, k4 = i & 31;
      *(float4*)&hs[b * 132 + k4 * 4] = v;
    }
    // prefetch x-gates (independent of hs)
    const float* xg = g_Xg + ((size_t)t * B_ + b0) * GATES;
    float x0[4], x1[4];
#pragma unroll
    for (int g = 0; g < 4; g++) {
      x0[g] = xg[g * HID_ + jg];
      x1[g] = xg[GATES + g * HID_ + jg];
    }
    __syncthreads();

    float a0[4] = {0.f, 0.f, 0.f, 0.f};
    float a1[4] = {0.f, 0.f, 0.f, 0.f};
    const float* h0p = hs + (2 * bp) * 132;
    const float* h1p = h0p + 132;
#pragma unroll 8
    for (int k = 0; k < HID_; k += 4) {
      float4 ha = *(const float4*)(h0p + k);
      float4 hb = *(const float4*)(h1p + k);
#pragma unroll
      for (int g = 0; g < 4; g++) {
        float4 w = *(const float4*)&Ws[(g * 8 + jl) * 132 + k];
        a0[g] += ha.x * w.x + ha.y * w.y + ha.z * w.z + ha.w * w.w;
        a1[g] += hb.x * w.x + hb.y * w.y + hb.z * w.z + hb.w * w.w;
      }
    }

    // elementwise LSTM cell (c in registers)
    float i0 = 1.f / (1.f + __expf(-(a0[0] + x0[0])));
    float f0 = 1.f / (1.f + __expf(-(a0[1] + x0[1])));
    float g0 = tanhf(a0[2] + x0[2]);
    float o0 = 1.f / (1.f + __expf(-(a0[3] + x0[3])));
    c0 = f0 * c0 + i0 * g0;
    float h0v = o0 * tanhf(c0);

    float i1 = 1.f / (1.f + __expf(-(a1[0] + x1[0])));
    float f1 = 1.f / (1.f + __expf(-(a1[1] + x1[1])));
    float g1 = tanhf(a1[2] + x1[2]);
    float o1 = 1.f / (1.f + __expf(-(a1[3] + x1[3])));
    c1 = f1 * c1 + i1 * g1;
    float h1v = o1 * tanhf(c1);

    if (t == T_ - 1) {
      out[b0 * HID_ + jg]        = h0v;
      out[(b0 + 1) * HID_ + jg]  = h1v;
    } else {
      float* h_out = g_h[(t + 1) & 1];
      h_out[b0 * HID_ + jg]       = h0v;
      h_out[(b0 + 1) * HID_ + jg] = h1v;

      // grid barrier (all 128 CTAs co-resident)
      __syncthreads();
      if (tid == 0) {
        __threadfence();
        unsigned target = (unsigned)(t + 1) * NCTA;
        unsigned old = atomicAdd(&g_arrive, 1u);
        if (old == target - 1u) {
          g_release = target;
        } else {
          while (g_release < target) { }
        }
        __threadfence();
      }
      __syncthreads();
    }
  }
}

// ---------------------------------------------------------------------------
__global__ void init_kernel(const float* __restrict__ h0) {
  int i = blockIdx.x * blockDim.x + threadIdx.x;   // 32768 threads
  g_h[0][i] = h0[i];
  if (i == 0) { g_arrive = 0u; g_release = 0u; }
}

// ---------------------------------------------------------------------------
extern "C" void kernel_launch(void* const* d_in, const int* in_sizes, int n_in,
                              void* d_out, int out_size) {
  const int*   text   = (const int*)  d_in[0];
  const float* h0     = (const float*)d_in[1];
  const float* emb    = (const float*)d_in[2];
  const float* conv_w = (const float*)d_in[3];
  const float* conv_b = (const float*)d_in[4];
  const float* w_ih   = (const float*)d_in[5];
  const float* w_hh   = (const float*)d_in[6];
  const float* b_ih   = (const float*)d_in[7];
  const float* b_hh   = (const float*)d_in[8];

  // K0: gather embeddings
  gather_kernel<<<(B_ * S_ * 64) / 256, 256>>>(text, emb);

  // K1: conv as GEMM [130048 x 1280] x [1280 x 256] + bias + relu
  sgemm_kernel<true ><<<dim3(NF_   / 128, M_ / 128), 256>>>(
      conv_w, conv_b, nullptr, KCONV, NF_);

  // K2: x-gates GEMM [130048 x 256] x [256 x 512] + b_ih + b_hh
  sgemm_kernel<false><<<dim3(GATES / 128, M_ / 128), 256>>>(
      w_ih, b_ih, b_hh, NF_, GATES);

  // K3: whole recurrence in ONE persistent launch
  init_kernel<<<128, 256>>>(h0);
  lstm_persist_kernel<<<NCTA, 128>>>(w_hh, (float*)d_out);
}

// round 4
// speedup vs baseline: 1.4936x; 1.0068x over previous
#include <cuda_runtime.h>
#include <cstdint>
#include <cstddef>

// Problem constants
#define B_    256
#define S_    512
#define EMB_  256
#define KER_  5
#define NF_   256
#define HID_  128
#define T_    508            // S - KER + 1
#define M_    (T_ * B_)      // 130048 rows (r = t*B + b)
#define KCONV (KER_ * EMB_)  // 1280
#define GATES 512            // 4*HID

// Scratch (static __device__ arrays: allocation-free per harness rules)
__device__ float g_E [(size_t)B_ * S_ * EMB_];   // embedded text [b][s][e]
__device__ float g_F [(size_t)M_ * NF_];         // conv+relu    [r][nf]
__device__ float g_Xg[(size_t)M_ * GATES];       // x-gates+bias [r][4H]
__device__ float g_h [2][B_ * HID_];             // ping-pong hidden state

// ---------------------------------------------------------------------------
// K0: embedding gather. E[b][s][:] = emb[text[b][s]][:]
// ---------------------------------------------------------------------------
__global__ void gather_kernel(const int* __restrict__ text,
                              const float* __restrict__ emb) {
  int idx = blockIdx.x * blockDim.x + threadIdx.x;   // over B*S*64 float4
  int row = idx >> 6;
  int c4  = idx & 63;
  int tok = text[row];
  ((float4*)g_E)[(size_t)row * 64 + c4] =
      ((const float4*)emb)[(size_t)tok * 64 + c4];
}

// ---------------------------------------------------------------------------
// K1/K2: tiled SGEMM, BM=BN=128, BK=16, 128 threads, 16x8 per thread
// (0.75 B smem / FMA -> LDS pipe no longer co-limits with FFMA).
// Double-buffered smem, one __syncthreads per k-tile, 2 CTAs/SM.
//   IS_CONV: A row r -> &g_E[((r&255)*S + (r>>8)) * EMB]  (windows contiguous)
//            epilogue: relu(acc + conv_b[n]) -> g_F
//   else   : A row r -> &g_F[r*256], epilogue: acc + b_ih + b_hh -> g_Xg
//   W is [N][K] row-major.
// ---------------------------------------------------------------------------
template<bool IS_CONV>
__global__ void __launch_bounds__(128, 2)
sgemm_kernel(const float* __restrict__ W,
             const float* __restrict__ bias0,
             const float* __restrict__ bias1,
             int Kdim, int Ndim) {
  __shared__ float As[2][16][128];
  __shared__ float Bs[2][16][128];

  const int tid  = threadIdx.x;
  const int row0 = blockIdx.y * 128;
  const int col0 = blockIdx.x * 128;
  const int tr   = (tid >> 4) << 4;   // 0..112, 16 rows per thread
  const int tc   = (tid & 15) << 3;   // 0..120, 8 cols per thread
  const int ms   = tid >> 2;          // staged row 0..31 (+32k)
  const int kq   = (tid & 3) * 4;     // staged k sub-offset

  float acc[16][8];
#pragma unroll
  for (int i = 0; i < 16; i++)
#pragma unroll
    for (int j = 0; j < 8; j++) acc[i][j] = 0.f;

  const float* Abase = IS_CONV ? g_E : g_F;

  size_t aoff[4], boff[4];
#pragma unroll
  for (int i = 0; i < 4; i++) {
    int m = ms + i * 32;
    int r = row0 + m;
    if (IS_CONV) {
      int b = r & 255, t = r >> 8;
      aoff[i] = ((size_t)b * S_ + t) * EMB_;
    } else {
      aoff[i] = (size_t)r * Kdim;
    }
    boff[i] = (size_t)(col0 + m) * Kdim;
  }

  const int KT = Kdim >> 4;

  // prologue: tile 0 -> smem[0]
#pragma unroll
  for (int i = 0; i < 4; i++) {
    int m = ms + i * 32;
    float4 va = *(const float4*)(Abase + aoff[i] + kq);
    float4 vb = *(const float4*)(W + boff[i] + kq);
    As[0][kq + 0][m] = va.x; As[0][kq + 1][m] = va.y;
    As[0][kq + 2][m] = va.z; As[0][kq + 3][m] = va.w;
    Bs[0][kq + 0][m] = vb.x; Bs[0][kq + 1][m] = vb.y;
    Bs[0][kq + 2][m] = vb.z; Bs[0][kq + 3][m] = vb.w;
  }
  __syncthreads();

  for (int kt = 0; kt < KT; kt++) {
    const int cur = kt & 1;
    float4 pa[4], pb[4];
    const bool pf = (kt + 1 < KT);
    if (pf) {
      int k0 = (kt + 1) << 4;
#pragma unroll
      for (int i = 0; i < 4; i++) {
        pa[i] = *(const float4*)(Abase + aoff[i] + k0 + kq);
        pb[i] = *(const float4*)(W + boff[i] + k0 + kq);
      }
    }
#pragma unroll
    for (int kk = 0; kk < 16; kk++) {
      float a[16], b[8];
      *(float4*)&a[ 0] = *(const float4*)&As[cur][kk][tr     ];
      *(float4*)&a[ 4] = *(const float4*)&As[cur][kk][tr +  4];
      *(float4*)&a[ 8] = *(const float4*)&As[cur][kk][tr +  8];
      *(float4*)&a[12] = *(const float4*)&As[cur][kk][tr + 12];
      *(float4*)&b[ 0] = *(const float4*)&Bs[cur][kk][tc     ];
      *(float4*)&b[ 4] = *(const float4*)&Bs[cur][kk][tc +  4];
#pragma unroll
      for (int i = 0; i < 16; i++)
#pragma unroll
        for (int j = 0; j < 8; j++) acc[i][j] += a[i] * b[j];
    }
    if (pf) {
      const int nxt = cur ^ 1;
#pragma unroll
      for (int i = 0; i < 4; i++) {
        int m = ms + i * 32;
        As[nxt][kq + 0][m] = pa[i].x; As[nxt][kq + 1][m] = pa[i].y;
        As[nxt][kq + 2][m] = pa[i].z; As[nxt][kq + 3][m] = pa[i].w;
        Bs[nxt][kq + 0][m] = pb[i].x; Bs[nxt][kq + 1][m] = pb[i].y;
        Bs[nxt][kq + 2][m] = pb[i].z; Bs[nxt][kq + 3][m] = pb[i].w;
      }
    }
    __syncthreads();
  }

  float* C = IS_CONV ? g_F : g_Xg;
#pragma unroll
  for (int i = 0; i < 16; i++) {
    size_t crow = (size_t)(row0 + tr + i) * Ndim;
#pragma unroll
    for (int j = 0; j < 8; j++) {
      int n = col0 + tc + j;
      float v = acc[i][j] + bias0[n];
      if (IS_CONV) v = fmaxf(v, 0.f);
      else         v += bias1[n];
      C[crow + n] = v;
    }
  }
}

// ---------------------------------------------------------------------------
// K3: persistent LSTM recurrence, clustered.
// Grid 128 CTAs x 128 threads; CTA = 16 batch x 16 hidden.
// Cluster of 8 = the 8 j-tile CTAs sharing one batch tile (batch tiles are
// INDEPENDENT chains -> only these 8 must sync; barrier.cluster ~500cyc
// replaces the serialized global atomic barrier, and the 8 clusters decouple).
// W_hh tile resident in smem for all 508 steps; c in REGISTERS; h ping-pongs
// through L2 (__ldcg). Padded smem rows (stride 132) keep LDS conflicts <=2-way.
// ---------------------------------------------------------------------------
__global__ void __launch_bounds__(128, 1) __cluster_dims__(8, 1, 1)
lstm_persist_kernel(const float* __restrict__ w_hh,
                    const float* __restrict__ h0,
                    float* __restrict__ out) {
  __shared__ float hs[16 * 132];     // h tile [b][k], padded
  __shared__ float Ws[64 * 132];     // W tile [g*16+jj][k], padded

  const int tid = threadIdx.x;
  const int jt  = blockIdx.x & 7;    // hidden tile within cluster (16 units)
  const int bt  = blockIdx.x >> 3;   // batch tile (16 rows), 16 tiles

  // Load W_hh tile once (4 gates x 16 j x 128 k = 2048 float4)
  for (int i = tid; i < 2048; i += 128) {
    int rowi = i >> 5, k4 = i & 31;              // rowi = g*16 + jj
    int g = rowi >> 4, jj = rowi & 15;
    float4 v = ((const float4*)w_hh)[(size_t)(g * 128 + jt * 16 + jj) * 32 + k4];
    *(float4*)&Ws[rowi * 132 + k4 * 4] = v;
  }

  const int jl = tid & 15;           // hidden within tile
  const int bp = tid >> 4;           // 0..7 -> batch pair
  const int jg = jt * 16 + jl;       // global hidden index
  const int b0 = bt * 16 + 2 * bp;   // global batch (first of pair)

  float c0 = 0.f, c1 = 0.f;          // cell state lives in registers

  for (int t = 0; t < T_; t++) {
    // stage h_in tile (16 x 128 floats); t=0 reads harness h_0 directly
    const float4* src = (t == 0)
        ? (const float4*)(h0     + bt * 16 * HID_)
        : (const float4*)(g_h[t & 1] + bt * 16 * HID_);
    for (int i = tid; i < 512; i += 128) {
      float4 v = __ldcg(src + i);
      int b = i >> 5, k4 = i & 31;
      *(float4*)&hs[b * 132 + k4 * 4] = v;
    }
    // prefetch x-gates (independent of hs)
    const float* xg = g_Xg + ((size_t)t * B_ + b0) * GATES;
    float x0[4], x1[4];
#pragma unroll
    for (int g = 0; g < 4; g++) {
      x0[g] = xg[g * HID_ + jg];
      x1[g] = xg[GATES + g * HID_ + jg];
    }
    __syncthreads();

    float a0[4] = {0.f, 0.f, 0.f, 0.f};
    float a1[4] = {0.f, 0.f, 0.f, 0.f};
    const float* h0p = hs + (2 * bp) * 132;
    const float* h1p = h0p + 132;
#pragma unroll 8
    for (int k = 0; k < HID_; k += 4) {
      float4 ha = *(const float4*)(h0p + k);
      float4 hb = *(const float4*)(h1p + k);
#pragma unroll
      for (int g = 0; g < 4; g++) {
        float4 w = *(const float4*)&Ws[(g * 16 + jl) * 132 + k];
        a0[g] += ha.x * w.x + ha.y * w.y + ha.z * w.z + ha.w * w.w;
        a1[g] += hb.x * w.x + hb.y * w.y + hb.z * w.z + hb.w * w.w;
      }
    }

    // elementwise LSTM cell (c in registers)
    float i0 = 1.f / (1.f + __expf(-(a0[0] + x0[0])));
    float f0 = 1.f / (1.f + __expf(-(a0[1] + x0[1])));
    float g0 = tanhf(a0[2] + x0[2]);
    float o0 = 1.f / (1.f + __expf(-(a0[3] + x0[3])));
    c0 = f0 * c0 + i0 * g0;
    float h0v = o0 * tanhf(c0);

    float i1 = 1.f / (1.f + __expf(-(a1[0] + x1[0])));
    float f1 = 1.f / (1.f + __expf(-(a1[1] + x1[1])));
    float g1 = tanhf(a1[2] + x1[2]);
    float o1 = 1.f / (1.f + __expf(-(a1[3] + x1[3])));
    c1 = f1 * c1 + i1 * g1;
    float h1v = o1 * tanhf(c1);

    if (t == T_ - 1) {
      out[b0 * HID_ + jg]        = h0v;
      out[(b0 + 1) * HID_ + jg]  = h1v;
    } else {
      float* h_out = g_h[(t + 1) & 1];
      h_out[b0 * HID_ + jg]       = h0v;
      h_out[(b0 + 1) * HID_ + jg] = h1v;

      // cluster barrier: arrive has release, wait has acquire semantics,
      // so prior STG are visible to the cluster's __ldcg after the wait.
      __syncthreads();
      asm volatile("barrier.cluster.arrive.aligned;" ::: "memory");
      asm volatile("barrier.cluster.wait.aligned;"   ::: "memory");
    }
  }
}

// ---------------------------------------------------------------------------
extern "C" void kernel_launch(void* const* d_in, const int* in_sizes, int n_in,
                              void* d_out, int out_size) {
  const int*   text   = (const int*)  d_in[0];
  const float* h0     = (const float*)d_in[1];
  const float* emb    = (const float*)d_in[2];
  const float* conv_w = (const float*)d_in[3];
  const float* conv_b = (const float*)d_in[4];
  const float* w_ih   = (const float*)d_in[5];
  const float* w_hh   = (const float*)d_in[6];
  const float* b_ih   = (const float*)d_in[7];
  const float* b_hh   = (const float*)d_in[8];

  // K0: gather embeddings
  gather_kernel<<<(B_ * S_ * 64) / 256, 256>>>(text, emb);

  // K1: conv as GEMM [130048 x 1280] x [1280 x 256] + bias + relu
  sgemm_kernel<true ><<<dim3(NF_   / 128, M_ / 128), 128>>>(
      conv_w, conv_b, nullptr, KCONV, NF_);

  // K2: x-gates GEMM [130048 x 256] x [256 x 512] + b_ih + b_hh
  sgemm_kernel<false><<<dim3(GATES / 128, M_ / 128), 128>>>(
      w_ih, b_ih, b_hh, NF_, GATES);

  // K3: whole recurrence in ONE persistent clustered launch
  lstm_persist_kernel<<<128, 128>>>(w_hh, h0, (float*)d_out);
}

// round 5
// speedup vs baseline: 1.6769x; 1.1227x over previous
#include <cuda_runtime.h>
#include <cstdint>
#include <cstddef>

// Problem constants
#define B_    256
#define S_    512
#define EMB_  256
#define KER_  5
#define NF_   256
#define HID_  128
#define T_    508            // S - KER + 1
#define M_    (T_ * B_)      // 130048 rows (r = t*B + b)
#define KCONV (KER_ * EMB_)  // 1280
#define GATES 512            // 4*HID

typedef unsigned long long u64;

// f32x2 packed-FMA helpers (ptxas never emits FFMA2 from C++; PTX-only)
__device__ __forceinline__ void fma2(u64& d, u64 a, u64 b) {
  asm("fma.rn.f32x2 %0, %1, %2, %0;" : "+l"(d) : "l"(a), "l"(b));
}
__device__ __forceinline__ u64 pack2(float x, float y) {
  u64 r; asm("mov.b64 %0, {%1, %2};" : "=l"(r) : "f"(x), "f"(y)); return r;
}
__device__ __forceinline__ float2 unpack2(u64 p) {
  float2 f; asm("mov.b64 {%0, %1}, %2;" : "=f"(f.x), "=f"(f.y) : "l"(p));
  return f;
}

// Scratch (static __device__ arrays: allocation-free per harness rules)
__device__ float g_E [(size_t)B_ * S_ * EMB_];   // embedded text [b][s][e]
__device__ float g_F [(size_t)M_ * NF_];         // conv+relu    [r][nf]
__device__ float g_Xg[(size_t)M_ * GATES];       // x-gates+bias [r][4H]
__device__ float g_h [2][B_ * HID_];             // ping-pong hidden state

// ---------------------------------------------------------------------------
// K0: embedding gather. E[b][s][:] = emb[text[b][s]][:]
// ---------------------------------------------------------------------------
__global__ void gather_kernel(const int* __restrict__ text,
                              const float* __restrict__ emb) {
  int idx = blockIdx.x * blockDim.x + threadIdx.x;   // over B*S*64 float4
  int row = idx >> 6;
  int c4  = idx & 63;
  int tok = text[row];
  ((float4*)g_E)[(size_t)row * 64 + c4] =
      ((const float4*)emb)[(size_t)tok * 64 + c4];
}

// ---------------------------------------------------------------------------
// K1/K2: tiled SGEMM with packed f32x2 FMAs (FFMA2 -> 128 MAC/cyc/SM vs 64
// for 3-reg FFMA). BM=BN=128, BK=16, 128 threads, 16x8/thread as 8 row-pair
// u64 accumulators x 8 cols. A row-pairs come free from LDS.128; B values
// duplicated into u64 via mov.b64 (alu pipe, hidden under fma pipe).
// Double-buffered smem, one __syncthreads per k-tile.
//   IS_CONV: A row r -> &g_E[((r&255)*S + (r>>8)) * EMB]  (windows contiguous)
//            epilogue: relu(acc + conv_b[n]) -> g_F
//   else   : A row r -> &g_F[r*256], epilogue: acc + b_ih + b_hh -> g_Xg
//   W is [N][K] row-major.
// ---------------------------------------------------------------------------
template<bool IS_CONV>
__global__ void __launch_bounds__(128, 2)
sgemm_kernel(const float* __restrict__ W,
             const float* __restrict__ bias0,
             const float* __restrict__ bias1,
             int Kdim, int Ndim) {
  __shared__ float As[2][16][128];
  __shared__ float Bs[2][16][128];

  const int tid  = threadIdx.x;
  const int row0 = blockIdx.y * 128;
  const int col0 = blockIdx.x * 128;
  const int tr   = (tid >> 4) << 4;   // 0..112, 16 rows (8 pairs) per thread
  const int tc   = (tid & 15) << 3;   // 0..120, 8 cols per thread
  const int ms   = tid >> 2;          // staged row 0..31 (+32k)
  const int kq   = (tid & 3) * 4;     // staged k sub-offset

  u64 acc2[8][8];                     // [row-pair][col] packed {r_even,r_odd}
#pragma unroll
  for (int i = 0; i < 8; i++)
#pragma unroll
    for (int j = 0; j < 8; j++) acc2[i][j] = 0ull;

  const float* Abase = IS_CONV ? g_E : g_F;

  size_t aoff[4], boff[4];
#pragma unroll
  for (int i = 0; i < 4; i++) {
    int m = ms + i * 32;
    int r = row0 + m;
    if (IS_CONV) {
      int b = r & 255, t = r >> 8;
      aoff[i] = ((size_t)b * S_ + t) * EMB_;
    } else {
      aoff[i] = (size_t)r * Kdim;
    }
    boff[i] = (size_t)(col0 + m) * Kdim;
  }

  const int KT = Kdim >> 4;

  // prologue: tile 0 -> smem[0]
#pragma unroll
  for (int i = 0; i < 4; i++) {
    int m = ms + i * 32;
    float4 va = *(const float4*)(Abase + aoff[i] + kq);
    float4 vb = *(const float4*)(W + boff[i] + kq);
    As[0][kq + 0][m] = va.x; As[0][kq + 1][m] = va.y;
    As[0][kq + 2][m] = va.z; As[0][kq + 3][m] = va.w;
    Bs[0][kq + 0][m] = vb.x; Bs[0][kq + 1][m] = vb.y;
    Bs[0][kq + 2][m] = vb.z; Bs[0][kq + 3][m] = vb.w;
  }
  __syncthreads();

  for (int kt = 0; kt < KT; kt++) {
    const int cur = kt & 1;
    float4 pa[4], pb[4];
    const bool pf = (kt + 1 < KT);
    if (pf) {
      int k0 = (kt + 1) << 4;
#pragma unroll
      for (int i = 0; i < 4; i++) {
        pa[i] = *(const float4*)(Abase + aoff[i] + k0 + kq);
        pb[i] = *(const float4*)(W + boff[i] + k0 + kq);
      }
    }
#pragma unroll
    for (int kk = 0; kk < 16; kk++) {
      ulonglong2 a01 = *(const ulonglong2*)&As[cur][kk][tr];
      ulonglong2 a23 = *(const ulonglong2*)&As[cur][kk][tr +  4];
      ulonglong2 a45 = *(const ulonglong2*)&As[cur][kk][tr +  8];
      ulonglong2 a67 = *(const ulonglong2*)&As[cur][kk][tr + 12];
      u64 av[8] = {a01.x, a01.y, a23.x, a23.y, a45.x, a45.y, a67.x, a67.y};
      float4 b03 = *(const float4*)&Bs[cur][kk][tc];
      float4 b47 = *(const float4*)&Bs[cur][kk][tc + 4];
      u64 bd[8];
      bd[0] = pack2(b03.x, b03.x); bd[1] = pack2(b03.y, b03.y);
      bd[2] = pack2(b03.z, b03.z); bd[3] = pack2(b03.w, b03.w);
      bd[4] = pack2(b47.x, b47.x); bd[5] = pack2(b47.y, b47.y);
      bd[6] = pack2(b47.z, b47.z); bd[7] = pack2(b47.w, b47.w);
#pragma unroll
      for (int i = 0; i < 8; i++)
#pragma unroll
        for (int j = 0; j < 8; j++) fma2(acc2[i][j], av[i], bd[j]);
    }
    if (pf) {
      const int nxt = cur ^ 1;
#pragma unroll
      for (int i = 0; i < 4; i++) {
        int m = ms + i * 32;
        As[nxt][kq + 0][m] = pa[i].x; As[nxt][kq + 1][m] = pa[i].y;
        As[nxt][kq + 2][m] = pa[i].z; As[nxt][kq + 3][m] = pa[i].w;
        Bs[nxt][kq + 0][m] = pb[i].x; Bs[nxt][kq + 1][m] = pb[i].y;
        Bs[nxt][kq + 2][m] = pb[i].z; Bs[nxt][kq + 3][m] = pb[i].w;
      }
    }
    __syncthreads();
  }

  float* C = IS_CONV ? g_F : g_Xg;
#pragma unroll
  for (int i = 0; i < 8; i++) {       // row pair i -> rows tr+2i, tr+2i+1
    float vlo[8], vhi[8];
#pragma unroll
    for (int j = 0; j < 8; j++) {
      int n = col0 + tc + j;
      float2 p = unpack2(acc2[i][j]);
      float a = p.x + bias0[n];
      float b = p.y + bias0[n];
      if (IS_CONV) { a = fmaxf(a, 0.f); b = fmaxf(b, 0.f); }
      else         { a += bias1[n];     b += bias1[n]; }
      vlo[j] = a; vhi[j] = b;
    }
    float* c0 = &C[(size_t)(row0 + tr + 2 * i)     * Ndim + col0 + tc];
    float* c1 = &C[(size_t)(row0 + tr + 2 * i + 1) * Ndim + col0 + tc];
    *(float4*)(c0)     = *(float4*)&vlo[0];
    *(float4*)(c0 + 4) = *(float4*)&vlo[4];
    *(float4*)(c1)     = *(float4*)&vhi[0];
    *(float4*)(c1 + 4) = *(float4*)&vhi[4];
  }
}

// ---------------------------------------------------------------------------
// K3: persistent clustered LSTM recurrence with f32x2 gate-pair FMAs.
// Grid 128 CTAs x 128 threads; CTA = 16 batch x 16 hidden; cluster of 8 =
// the j-tiles of one batch tile (independent chains -> cluster barrier only).
// W_hh resident in smem as [k][jl][4 gates] so one LDS.128 yields the two
// u64 gate-pair operands {wi,wf},{wg,wo}. h staged DUPLICATED ({h,h} pairs)
// so broadcast operands load directly with zero packing movs. c in registers.
// Smem exactly 48KB.
// ---------------------------------------------------------------------------
__global__ void __launch_bounds__(128, 1) __cluster_dims__(8, 1, 1)
lstm_persist_kernel(const float* __restrict__ w_hh,
                    const float* __restrict__ h0,
                    float* __restrict__ out) {
  __shared__ float hs2[16 * 256];    // h tile duplicated: [b][2k..2k+1]={h,h}
  __shared__ float Wp [128 * 64];    // [k][jl][g], g-major pairs

  const int tid = threadIdx.x;
  const int jt  = blockIdx.x & 7;    // hidden tile within cluster (16 units)
  const int bt  = blockIdx.x >> 3;   // batch tile (16 rows), 16 tiles

  // Load W_hh into [k][jl][g] layout once (8192 floats)
  for (int i = tid; i < 8192; i += 128) {
    int k = i >> 6, rem = i & 63, jl = rem >> 2, g = rem & 3;
    Wp[i] = w_hh[(size_t)(g * 128 + jt * 16 + jl) * 128 + k];
  }

  const int jl = tid & 15;           // hidden within tile
  const int bp = tid >> 4;           // 0..7 -> batch pair
  const int jg = jt * 16 + jl;       // global hidden index
  const int b0 = bt * 16 + 2 * bp;   // global batch (first of pair)

  float c0 = 0.f, c1 = 0.f;          // cell state lives in registers

  for (int t = 0; t < T_; t++) {
    // prefetch x-gates early (consumed after the inner loop)
    const float* xg = g_Xg + ((size_t)t * B_ + b0) * GATES;
    float x0[4], x1[4];
#pragma unroll
    for (int g = 0; g < 4; g++) {
      x0[g] = xg[g * HID_ + jg];
      x1[g] = xg[GATES + g * HID_ + jg];
    }

    // stage h_in tile, duplicated; t=0 reads harness h_0 directly
    const float4* src = (t == 0)
        ? (const float4*)(h0         + bt * 16 * HID_)
        : (const float4*)(g_h[t & 1] + bt * 16 * HID_);
    for (int i = tid; i < 512; i += 128) {
      float4 v = __ldcg(src + i);
      int b = i >> 5, k4 = i & 31;
      float* d = &hs2[b * 256 + k4 * 8];
      *(float4*)(d)     = make_float4(v.x, v.x, v.y, v.y);
      *(float4*)(d + 4) = make_float4(v.z, v.z, v.w, v.w);
    }
    __syncthreads();

    u64 aA0 = 0ull, aB0 = 0ull, aA1 = 0ull, aB1 = 0ull;   // {i,f},{g,o} x 2b
    const float* h0r = &hs2[(2 * bp)     * 256];
    const float* h1r = &hs2[(2 * bp + 1) * 256];
#pragma unroll 8
    for (int k = 0; k < HID_; k += 4) {
      ulonglong2 pa  = *(const ulonglong2*)(h0r + 2 * k);
      ulonglong2 pa2 = *(const ulonglong2*)(h0r + 2 * k + 4);
      ulonglong2 pb  = *(const ulonglong2*)(h1r + 2 * k);
      ulonglong2 pb2 = *(const ulonglong2*)(h1r + 2 * k + 4);
      u64 hd0[4] = {pa.x, pa.y, pa2.x, pa2.y};
      u64 hd1[4] = {pb.x, pb.y, pb2.x, pb2.y};
#pragma unroll
      for (int kk = 0; kk < 4; kk++) {
        ulonglong2 w = *(const ulonglong2*)&Wp[(k + kk) * 64 + jl * 4];
        fma2(aA0, hd0[kk], w.x); fma2(aB0, hd0[kk], w.y);
        fma2(aA1, hd1[kk], w.x); fma2(aB1, hd1[kk], w.y);
      }
    }

    // elementwise LSTM cell (c in registers)
    float2 pA0 = unpack2(aA0), pB0 = unpack2(aB0);
    float2 pA1 = unpack2(aA1), pB1 = unpack2(aB1);

    float i0 = 1.f / (1.f + __expf(-(pA0.x + x0[0])));
    float f0 = 1.f / (1.f + __expf(-(pA0.y + x0[1])));
    float g0 = tanhf(pB0.x + x0[2]);
    float o0 = 1.f / (1.f + __expf(-(pB0.y + x0[3])));
    c0 = f0 * c0 + i0 * g0;
    float h0v = o0 * tanhf(c0);

    float i1 = 1.f / (1.f + __expf(-(pA1.x + x1[0])));
    float f1 = 1.f / (1.f + __expf(-(pA1.y + x1[1])));
    float g1 = tanhf(pB1.x + x1[2]);
    float o1 = 1.f / (1.f + __expf(-(pB1.y + x1[3])));
    c1 = f1 * c1 + i1 * g1;
    float h1v = o1 * tanhf(c1);

    if (t == T_ - 1) {
      out[b0 * HID_ + jg]        = h0v;
      out[(b0 + 1) * HID_ + jg]  = h1v;
    } else {
      float* h_out = g_h[(t + 1) & 1];
      h_out[b0 * HID_ + jg]       = h0v;
      h_out[(b0 + 1) * HID_ + jg] = h1v;

      // cluster barrier: arrive=release, wait=acquire -> prior STG visible
      // to the cluster's __ldcg after the wait.
      __syncthreads();
      asm volatile("barrier.cluster.arrive.aligned;" ::: "memory");
      asm volatile("barrier.cluster.wait.aligned;"   ::: "memory");
    }
  }
}

// ---------------------------------------------------------------------------
extern "C" void kernel_launch(void* const* d_in, const int* in_sizes, int n_in,
                              void* d_out, int out_size) {
  const int*   text   = (const int*)  d_in[0];
  const float* h0     = (const float*)d_in[1];
  const float* emb    = (const float*)d_in[2];
  const float* conv_w = (const float*)d_in[3];
  const float* conv_b = (const float*)d_in[4];
  const float* w_ih   = (const float*)d_in[5];
  const float* w_hh   = (const float*)d_in[6];
  const float* b_ih   = (const float*)d_in[7];
  const float* b_hh   = (const float*)d_in[8];

  // K0: gather embeddings
  gather_kernel<<<(B_ * S_ * 64) / 256, 256>>>(text, emb);

  // K1: conv as GEMM [130048 x 1280] x [1280 x 256] + bias + relu
  sgemm_kernel<true ><<<dim3(NF_   / 128, M_ / 128), 128>>>(
      conv_w, conv_b, nullptr, KCONV, NF_);

  // K2: x-gates GEMM [130048 x 256] x [256 x 512] + b_ih + b_hh
  sgemm_kernel<false><<<dim3(GATES / 128, M_ / 128), 128>>>(
      w_ih, b_ih, b_hh, NF_, GATES);

  // K3: whole recurrence in ONE persistent clustered launch
  lstm_persist_kernel<<<128, 128>>>(w_hh, h0, (float*)d_out);
}

// round 14
// speedup vs baseline: 2.1072x; 1.2566x over previous
#include <cuda_runtime.h>
#include <cstdint>
#include <cstddef>

// Problem constants
#define B_    256
#define S_    512
#define EMB_  256
#define KER_  5
#define NF_   256
#define HID_  128
#define T_    508            // S - KER + 1
#define M_    (T_ * B_)      // 130048 rows (r = t*B + b)
#define KCONV (KER_ * EMB_)  // 1280
#define GATES 512            // 4*HID

typedef unsigned long long u64;

// ---------------- f32x2 packed-FMA helpers (proven clean in R5) ------------
__device__ __forceinline__ void fma2(u64& d, u64 a, u64 b) {
  asm("fma.rn.f32x2 %0, %1, %2, %0;" : "+l"(d) : "l"(a), "l"(b));
}
__device__ __forceinline__ u64 pack2(float x, float y) {
  u64 r; asm("mov.b64 %0, {%1, %2};" : "=l"(r) : "f"(x), "f"(y)); return r;
}
__device__ __forceinline__ float2 unpack2(u64 p) {
  float2 f; asm("mov.b64 {%0, %1}, %2;" : "=f"(f.x), "=f"(f.y) : "l"(p));
  return f;
}
__device__ __forceinline__ uint32_t smem_addr_u32(const void* p) {
  uint32_t a;
  asm("{ .reg .u64 t; cvta.to.shared.u64 t, %1; cvt.u32.u64 %0, t; }"
      : "=r"(a) : "l"(p));
  return a;
}
__device__ __forceinline__ uint32_t cluster_rank() {
  uint32_t r; asm("mov.u32 %0, %%cluster_ctarank;" : "=r"(r)); return r;
}
__device__ __forceinline__ uint32_t mapa_u32(uint32_t la, uint32_t rank) {
  uint32_t r;
  asm("mapa.shared::cluster.u32 %0, %1, %2;" : "=r"(r) : "r"(la), "r"(rank));
  return r;
}
__device__ __forceinline__ void st_cluster_u64(uint32_t addr, u64 v) {
  asm volatile("st.shared::cluster.u64 [%0], %1;" :: "r"(addr), "l"(v)
               : "memory");
}

// Scratch (fp32 only; exactly the R5-passing set)
__device__ float g_E [(size_t)B_ * S_ * EMB_];   // embedded text [b][s][e]
__device__ float g_F [(size_t)M_ * NF_];         // conv+relu    [r][nf]
__device__ float g_Xg[(size_t)M_ * GATES];       // x-gates+bias [r][4H]

// ---------------------------------------------------------------------------
// K0: embedding gather (verbatim R5-passing)
// ---------------------------------------------------------------------------
__global__ void gather_kernel(const int* __restrict__ text,
                              const float* __restrict__ emb) {
  int idx = blockIdx.x * blockDim.x + threadIdx.x;   // over B*S*64 float4
  int row = idx >> 6;
  int c4  = idx & 63;
  int tok = text[row];
  ((float4*)g_E)[(size_t)row * 64 + c4] =
      ((const float4*)emb)[(size_t)tok * 64 + c4];
}

// ---------------------------------------------------------------------------
// K1/K2: FFMA2 SGEMM (verbatim R5-passing build: BM=BN=128, BK=16, 128 thr,
// 16x8/thread as 8 row-pair u64 accumulators, double-buffered smem).
// ---------------------------------------------------------------------------
template<bool IS_CONV>
__global__ void __launch_bounds__(128, 2)
sgemm_kernel(const float* __restrict__ W,
             const float* __restrict__ bias0,
             const float* __restrict__ bias1,
             int Kdim, int Ndim) {
  __shared__ float As[2][16][128];
  __shared__ float Bs[2][16][128];

  const int tid  = threadIdx.x;
  const int row0 = blockIdx.y * 128;
  const int col0 = blockIdx.x * 128;
  const int tr   = (tid >> 4) << 4;
  const int tc   = (tid & 15) << 3;
  const int ms   = tid >> 2;
  const int kq   = (tid & 3) * 4;

  u64 acc2[8][8];
#pragma unroll
  for (int i = 0; i < 8; i++)
#pragma unroll
    for (int j = 0; j < 8; j++) acc2[i][j] = 0ull;

  const float* Abase = IS_CONV ? g_E : g_F;

  size_t aoff[4], boff[4];
#pragma unroll
  for (int i = 0; i < 4; i++) {
    int m = ms + i * 32;
    int r = row0 + m;
    if (IS_CONV) {
      int b = r & 255, t = r >> 8;
      aoff[i] = ((size_t)b * S_ + t) * EMB_;
    } else {
      aoff[i] = (size_t)r * Kdim;
    }
    boff[i] = (size_t)(col0 + m) * Kdim;
  }

  const int KT = Kdim >> 4;

#pragma unroll
  for (int i = 0; i < 4; i++) {
    int m = ms + i * 32;
    float4 va = *(const float4*)(Abase + aoff[i] + kq);
    float4 vb = *(const float4*)(W + boff[i] + kq);
    As[0][kq + 0][m] = va.x; As[0][kq + 1][m] = va.y;
    As[0][kq + 2][m] = va.z; As[0][kq + 3][m] = va.w;
    Bs[0][kq + 0][m] = vb.x; Bs[0][kq + 1][m] = vb.y;
    Bs[0][kq + 2][m] = vb.z; Bs[0][kq + 3][m] = vb.w;
  }
  __syncthreads();

  for (int kt = 0; kt < KT; kt++) {
    const int cur = kt & 1;
    float4 pa[4], pb[4];
    const bool pf = (kt + 1 < KT);
    if (pf) {
      int k0 = (kt + 1) << 4;
#pragma unroll
      for (int i = 0; i < 4; i++) {
        pa[i] = *(const float4*)(Abase + aoff[i] + k0 + kq);
        pb[i] = *(const float4*)(W + boff[i] + k0 + kq);
      }
    }
#pragma unroll
    for (int kk = 0; kk < 16; kk++) {
      ulonglong2 a01 = *(const ulonglong2*)&As[cur][kk][tr];
      ulonglong2 a23 = *(const ulonglong2*)&As[cur][kk][tr +  4];
      ulonglong2 a45 = *(const ulonglong2*)&As[cur][kk][tr +  8];
      ulonglong2 a67 = *(const ulonglong2*)&As[cur][kk][tr + 12];
      u64 av[8] = {a01.x, a01.y, a23.x, a23.y, a45.x, a45.y, a67.x, a67.y};
      float4 b03 = *(const float4*)&Bs[cur][kk][tc];
      float4 b47 = *(const float4*)&Bs[cur][kk][tc + 4];
      u64 bd[8];
      bd[0] = pack2(b03.x, b03.x); bd[1] = pack2(b03.y, b03.y);
      bd[2] = pack2(b03.z, b03.z); bd[3] = pack2(b03.w, b03.w);
      bd[4] = pack2(b47.x, b47.x); bd[5] = pack2(b47.y, b47.y);
      bd[6] = pack2(b47.z, b47.z); bd[7] = pack2(b47.w, b47.w);
#pragma unroll
      for (int i = 0; i < 8; i++)
#pragma unroll
        for (int j = 0; j < 8; j++) fma2(acc2[i][j], av[i], bd[j]);
    }
    if (pf) {
      const int nxt = cur ^ 1;
#pragma unroll
      for (int i = 0; i < 4; i++) {
        int m = ms + i * 32;
        As[nxt][kq + 0][m] = pa[i].x; As[nxt][kq + 1][m] = pa[i].y;
        As[nxt][kq + 2][m] = pa[i].z; As[nxt][kq + 3][m] = pa[i].w;
        Bs[nxt][kq + 0][m] = pb[i].x; Bs[nxt][kq + 1][m] = pb[i].y;
        Bs[nxt][kq + 2][m] = pb[i].z; Bs[nxt][kq + 3][m] = pb[i].w;
      }
    }
    __syncthreads();
  }

  float* C = IS_CONV ? g_F : g_Xg;
#pragma unroll
  for (int i = 0; i < 8; i++) {
    float vlo[8], vhi[8];
#pragma unroll
    for (int j = 0; j < 8; j++) {
      int n = col0 + tc + j;
      float2 p = unpack2(acc2[i][j]);
      float a = p.x + bias0[n];
      float b = p.y + bias0[n];
      if (IS_CONV) { a = fmaxf(a, 0.f); b = fmaxf(b, 0.f); }
      else         { a += bias1[n];     b += bias1[n]; }
      vlo[j] = a; vhi[j] = b;
    }
    float* c0 = &C[(size_t)(row0 + tr + 2 * i)     * Ndim + col0 + tc];
    float* c1 = &C[(size_t)(row0 + tr + 2 * i + 1) * Ndim + col0 + tc];
    *(float4*)(c0)     = *(float4*)&vlo[0];
    *(float4*)(c0 + 4) = *(float4*)&vlo[4];
    *(float4*)(c1)     = *(float4*)&vhi[0];
    *(float4*)(c1 + 4) = *(float4*)&vhi[4];
  }
}

// ---------------------------------------------------------------------------
// K3: persistent LSTM recurrence, cluster-of-2 with DSMEM h exchange.
// 128 CTAs x 128 thr = 64 batch-tiles (4 batches) x 2 j-halves (64 j).
// W_hh half resident in smem FP32 (128KB, layout [k][jl][g]); h kept in a
// DOUBLE-BUFFERED duplicated {h,h} smem buffer (2x4x256 floats). Producers
// write next-step h into BOTH CTAs' buffers (local st + mapa/st.cluster);
// one 2-CTA barrier.cluster per step. No global traffic in the loop except
// x-gate reads. c stays in registers.
// ---------------------------------------------------------------------------
#define WP_FLOATS (128 * 64 * 4)             // 32768 floats = 128KB
#define HS_FLOATS (2 * 4 * 256)              // 2048 floats = 8KB
#define RSMEM     ((WP_FLOATS + HS_FLOATS) * 4)

__global__ void __launch_bounds__(128, 1) __cluster_dims__(2, 1, 1)
lstm2_kernel(const float* __restrict__ w_hh,
             const float* __restrict__ h0,
             float* __restrict__ out) {
  extern __shared__ float sm[];
  float* Wp = sm;                 // [k][jl][g], 64 jl of this half
  float* hs = sm + WP_FLOATS;     // [buf][b][2k..2k+1]

  const int tid = threadIdx.x;
  const int bid = blockIdx.x;
  const int jh  = bid & 1;        // hidden half (0..1)
  const int bt  = bid >> 1;       // batch tile (4 rows), 64 tiles
  const uint32_t peer = cluster_rank() ^ 1u;

  // stage W_hh half: Wp[(k*64 + jl)*4 + g] = w_hh[(g*128 + jh*64 + jl)*128 + k]
  for (int i = tid; i < WP_FLOATS; i += 128) {
    int k = i >> 8, rem = i & 255, jl = rem >> 2, g = rem & 3;
    Wp[i] = w_hh[(size_t)(g * 128 + jh * 64 + jl) * 128 + k];
  }

  // stage initial h (buffer 0, duplicated): 4 batches x 128 k
  {
    float4 v = ((const float4*)(h0 + bt * 4 * HID_))[tid];
    int b = tid >> 5, k4 = tid & 31;
    float* d = &hs[b * 256 + k4 * 8];
    *(float4*)(d)     = make_float4(v.x, v.x, v.y, v.y);
    *(float4*)(d + 4) = make_float4(v.z, v.z, v.w, v.w);
  }
  __syncthreads();

  const int jl = tid & 63;           // hidden within half
  const int bp = tid >> 6;           // 0..1 -> batch pair
  const int jg = jh * 64 + jl;       // global hidden index
  const int b0 = bt * 4 + 2 * bp;    // global batch (first of pair)
  const uint32_t hs_u32 = smem_addr_u32(hs);

  float c0 = 0.f, c1 = 0.f;

  for (int t = 0; t < T_; t++) {
    // prefetch x-gates (global; independent of smem state)
    const float* xg = g_Xg + ((size_t)t * B_ + b0) * GATES;
    float x0[4], x1[4];
#pragma unroll
    for (int g = 0; g < 4; g++) {
      x0[g] = xg[g * HID_ + jg];
      x1[g] = xg[GATES + g * HID_ + jg];
    }

    u64 aA0 = 0ull, aB0 = 0ull, aA1 = 0ull, aB1 = 0ull;
    const float* h0r = &hs[(t & 1) * 1024 + (2 * bp)     * 256];
    const float* h1r = &hs[(t & 1) * 1024 + (2 * bp + 1) * 256];
#pragma unroll 8
    for (int k = 0; k < HID_; k += 4) {
      ulonglong2 pa  = *(const ulonglong2*)(h0r + 2 * k);
      ulonglong2 pa2 = *(const ulonglong2*)(h0r + 2 * k + 4);
      ulonglong2 pb  = *(const ulonglong2*)(h1r + 2 * k);
      ulonglong2 pb2 = *(const ulonglong2*)(h1r + 2 * k + 4);
      u64 hd0[4] = {pa.x, pa.y, pa2.x, pa2.y};
      u64 hd1[4] = {pb.x, pb.y, pb2.x, pb2.y};
#pragma unroll
      for (int kk = 0; kk < 4; kk++) {
        ulonglong2 wv = *(const ulonglong2*)&Wp[((k + kk) * 64 + jl) * 4];
        fma2(aA0, hd0[kk], wv.x); fma2(aB0, hd0[kk], wv.y);
        fma2(aA1, hd1[kk], wv.x); fma2(aB1, hd1[kk], wv.y);
      }
    }

    float2 pA0 = unpack2(aA0), pB0 = unpack2(aB0);
    float2 pA1 = unpack2(aA1), pB1 = unpack2(aB1);

    float i0 = 1.f / (1.f + __expf(-(pA0.x + x0[0])));
    float f0 = 1.f / (1.f + __expf(-(pA0.y + x0[1])));
    float g0 = tanhf(pB0.x + x0[2]);
    float o0 = 1.f / (1.f + __expf(-(pB0.y + x0[3])));
    c0 = f0 * c0 + i0 * g0;
    float h0v = o0 * tanhf(c0);

    float i1 = 1.f / (1.f + __expf(-(pA1.x + x1[0])));
    float f1 = 1.f / (1.f + __expf(-(pA1.y + x1[1])));
    float g1 = tanhf(pB1.x + x1[2]);
    float o1 = 1.f / (1.f + __expf(-(pB1.y + x1[3])));
    c1 = f1 * c1 + i1 * g1;
    float h1v = o1 * tanhf(c1);

    if (t == T_ - 1) {
      out[b0 * HID_ + jg]        = h0v;
      out[(b0 + 1) * HID_ + jg]  = h1v;
    } else {
      // write h(t+1) duplicated into BOTH CTAs' buffer (t+1)&1.
      // Safe with ONE barrier/step: during step t nobody reads buf (t+1)&1.
      const int fo0 = ((t + 1) & 1) * 1024 + (2 * bp) * 256 + 2 * jg;
      const int fo1 = fo0 + 256;
      u64 p0 = pack2(h0v, h0v);
      u64 p1 = pack2(h1v, h1v);
      *(u64*)&hs[fo0] = p0;                              // local
      *(u64*)&hs[fo1] = p1;
      st_cluster_u64(mapa_u32(hs_u32 + fo0 * 4, peer), p0);   // peer (DSMEM)
      st_cluster_u64(mapa_u32(hs_u32 + fo1 * 4, peer), p1);

      // arrive = release (covers smem + DSMEM stores), wait = acquire
      __syncthreads();
      asm volatile("barrier.cluster.arrive.aligned;" ::: "memory");
      asm volatile("barrier.cluster.wait.aligned;"   ::: "memory");
    }
  }
}

// ---------------------------------------------------------------------------
extern "C" void kernel_launch(void* const* d_in, const int* in_sizes, int n_in,
                              void* d_out, int out_size) {
  const int*   text   = (const int*)  d_in[0];
  const float* h0     = (const float*)d_in[1];
  const float* emb    = (const float*)d_in[2];
  const float* conv_w = (const float*)d_in[3];
  const float* conv_b = (const float*)d_in[4];
  const float* w_ih   = (const float*)d_in[5];
  const float* w_hh   = (const float*)d_in[6];
  const float* b_ih   = (const float*)d_in[7];
  const float* b_hh   = (const float*)d_in[8];

  cudaFuncSetAttribute(lstm2_kernel,
                       cudaFuncAttributeMaxDynamicSharedMemorySize, RSMEM);

  // K0: gather embeddings
  gather_kernel<<<(B_ * S_ * 64) / 256, 256>>>(text, emb);

  // K1: conv as GEMM [130048 x 1280] x [1280 x 256] + bias + relu
  sgemm_kernel<true ><<<dim3(NF_   / 128, M_ / 128), 128>>>(
      conv_w, conv_b, nullptr, KCONV, NF_);

  // K2: x-gates GEMM [130048 x 256] x [256 x 512] + b_ih + b_hh
  sgemm_kernel<false><<<dim3(GATES / 128, M_ / 128), 128>>>(
      w_ih, b_ih, b_hh, NF_, GATES);

  // K3: whole recurrence in ONE persistent clustered launch (DSMEM exchange)
  lstm2_kernel<<<128, 128, RSMEM>>>(w_hh, h0, (float*)d_out);
}